// round 1
// baseline (speedup 1.0000x reference)
#include <cuda_runtime.h>
#include <cstdint>

// ---------------------------------------------------------------------------
// BatchedSequences: scatter concatenated rows S[T,F] into padded out[B,MAX,F],
// zero-filling the padding. Memory-bound copy; target is the HBM roofline.
// ---------------------------------------------------------------------------

#define MAX_B 8192
__device__ int       g_len[MAX_B];
__device__ long long g_off[MAX_B];

// Prologue: build per-batch length + prefix offset. Detects int32 vs int64
// sequence_lengths by checking whether the int32-sum equals T (total rows).
// Reads only B*4 bytes in the probe, which is in-bounds for both layouts.
__global__ void build_offsets_kernel(const void* __restrict__ lens_raw,
                                     int B, long long T) {
    if (blockIdx.x != 0 || threadIdx.x != 0) return;
    const int* v32 = (const int*)lens_raw;
    long long s32 = 0;
    for (int i = 0; i < B; ++i) s32 += (long long)v32[i];
    const bool is32 = (s32 == T);
    const long long* v64 = (const long long*)lens_raw;
    long long off = 0;
    for (int i = 0; i < B; ++i) {
        long long L = is32 ? (long long)v32[i] : v64[i];
        g_len[i] = (int)L;
        g_off[i] = off;
        off += L;
    }
}

// Main kernel: one float4 per thread, flat index over the output.
// idx -> (b, p, c); copy from input row off[b]+p if p < len[b], else zeros.
// Fully coalesced on both input and output. Streaming hints: data is
// touched exactly once, keep it out of L2's way.
template <int F4_C, int MAX_C>
__global__ void __launch_bounds__(256)
pad_scatter_kernel(const float4* __restrict__ in4,
                   float4* __restrict__ out4,
                   int total, int F4, int max_sl) {
    int idx = blockIdx.x * blockDim.x + threadIdx.x;
    if (idx >= total) return;

    int c, row, b, p;
    if (F4_C > 0) {           // compile-time fast path (shifts)
        c   = idx & (F4_C - 1);
        row = idx >> __popc(F4_C - 1);
        b   = row >> __popc(MAX_C - 1);
        p   = row & (MAX_C - 1);
    } else {                  // generic fallback
        c   = idx % F4;
        row = idx / F4;
        b   = row / max_sl;
        p   = row - b * max_sl;
    }

    float4 v = make_float4(0.f, 0.f, 0.f, 0.f);
    if (p < g_len[b]) {
        long long src = (g_off[b] + (long long)p) * (F4_C > 0 ? F4_C : F4) + c;
        v = __ldcs(&in4[src]);
    }
    __stcs(&out4[idx], v);
}

extern "C" void kernel_launch(void* const* d_in, const int* in_sizes, int n_in,
                              void* d_out, int out_size) {
    const int F  = 512;                      // feature dim (fixed instance)
    const int F4 = F / 4;                    // float4 per row
    const int B  = in_sizes[1];              // sequence_lengths element count
    const long long T = (long long)in_sizes[0] / F;
    const int max_sl = (int)((long long)out_size / ((long long)B * F));

    build_offsets_kernel<<<1, 1>>>(d_in[1], B, T);

    const int total = out_size / 4;          // float4 elements in output
    const int threads = 256;
    const int blocks = (total + threads - 1) / threads;

    if (F4 == 128 && max_sl == 4096) {
        pad_scatter_kernel<128, 4096><<<blocks, threads>>>(
            (const float4*)d_in[0], (float4*)d_out, total, F4, max_sl);
    } else {
        pad_scatter_kernel<0, 0><<<blocks, threads>>>(
            (const float4*)d_in[0], (float4*)d_out, total, F4, max_sl);
    }
}

// round 2
// speedup vs baseline: 1.0008x; 1.0008x over previous
#include <cuda_runtime.h>
#include <cstdint>

// ---------------------------------------------------------------------------
// BatchedSequences: scatter concatenated rows S[T,F] into padded out[B,MAX,F],
// zero-filling the padding. Pure data movement -> HBM roofline target.
// R2: 4x float4 per thread (MLP=4 batched loads), block-uniform batch index,
//     parallel prologue.
// ---------------------------------------------------------------------------

#define MAX_B 4096
__device__ int       g_len[MAX_B];
__device__ long long g_off[MAX_B];

// Prologue: parallel load of lengths (int32/int64 auto-detected by checking
// whether the int32 interpretation sums to T), then serial prefix over smem
// (cheap: B iterations over shared memory, no global latency in the loop).
__global__ void build_offsets_kernel(const void* __restrict__ lens_raw,
                                     int B, long long T) {
    __shared__ long long s32sum_sh;
    __shared__ long long v_sh[MAX_B > 1024 ? 1024 : MAX_B];
    const int t = threadIdx.x;
    const int* v32 = (const int*)lens_raw;
    const long long* v64 = (const long long*)lens_raw;

    // int32-sum probe (reads B*4 bytes, in-bounds for both layouts)
    if (t == 0) {
        long long s = 0;
        #pragma unroll 4
        for (int i = 0; i < B; ++i) s += (long long)v32[i];
        s32sum_sh = s;
    }
    __syncthreads();
    const bool is32 = (s32sum_sh == T);

    // parallel loads into smem (one pass; B <= 1024 covered by one block,
    // larger B falls back to strided loop)
    for (int i = t; i < B; i += blockDim.x)
        v_sh[i] = is32 ? (long long)v32[i] : v64[i];
    __syncthreads();

    if (t == 0) {
        long long off = 0;
        for (int i = 0; i < B; ++i) {
            long long L = v_sh[i];
            g_len[i] = (int)L;
            g_off[i] = off;
            off += L;
        }
    }
}

// Fast path: F4 and MAX are powers of two known at compile time.
// Each block handles 1024 contiguous float4 (256 thr x 4). Since 1024 divides
// MAX*F4, the batch index is block-uniform: len/off loaded once per block.
// The 4 loads per thread are independent and emitted front-first (MLP=4).
template <int F4_LOG2, int MAX_LOG2>
__global__ void __launch_bounds__(256)
pad_scatter4_kernel(const float4* __restrict__ in4,
                    float4* __restrict__ out4) {
    constexpr int F4 = 1 << F4_LOG2;
    constexpr int SEG_LOG2 = F4_LOG2 + MAX_LOG2;   // float4 per batch segment

    const int tid  = threadIdx.x;
    const int base = (int)blockIdx.x * 1024;       // <= 16.7M, fits int
    const int b    = base >> SEG_LOG2;
    const int len  = g_len[b];
    const int off  = (int)g_off[b];                // off*F4 fits int (T*F4 < 2^31)

    int   idx[4], p[4];
    float4 v[4];
    #pragma unroll
    for (int k = 0; k < 4; ++k) {
        idx[k] = base + tid + k * 256;
        p[k]   = (idx[k] >> F4_LOG2) & ((1 << MAX_LOG2) - 1);
        v[k]   = make_float4(0.f, 0.f, 0.f, 0.f);
    }
    #pragma unroll
    for (int k = 0; k < 4; ++k) {
        if (p[k] < len) {
            int c = idx[k] & (F4 - 1);
            v[k] = __ldcs(&in4[(off + p[k]) * F4 + c]);
        }
    }
    #pragma unroll
    for (int k = 0; k < 4; ++k)
        __stcs(&out4[idx[k]], v[k]);
}

// Generic fallback (any F4 / max_sl), one float4 per thread.
__global__ void __launch_bounds__(256)
pad_scatter_generic(const float4* __restrict__ in4,
                    float4* __restrict__ out4,
                    int total, int F4, int max_sl) {
    int idx = blockIdx.x * blockDim.x + threadIdx.x;
    if (idx >= total) return;
    int c   = idx % F4;
    int row = idx / F4;
    int b   = row / max_sl;
    int p   = row - b * max_sl;
    float4 v = make_float4(0.f, 0.f, 0.f, 0.f);
    if (p < g_len[b])
        v = __ldcs(&in4[(g_off[b] + (long long)p) * F4 + c]);
    __stcs(&out4[idx], v);
}

extern "C" void kernel_launch(void* const* d_in, const int* in_sizes, int n_in,
                              void* d_out, int out_size) {
    const int F  = 512;
    const int F4 = F / 4;                                    // 128
    const int B  = in_sizes[1];
    const long long T = (long long)in_sizes[0] / F;
    const int max_sl = (int)((long long)out_size / ((long long)B * F));

    build_offsets_kernel<<<1, 256>>>(d_in[1], B, T);

    const int total = out_size / 4;                          // float4 count
    if (F4 == 128 && max_sl == 4096 && (total % 1024) == 0) {
        pad_scatter4_kernel<7, 12><<<total / 1024, 256>>>(
            (const float4*)d_in[0], (float4*)d_out);
    } else {
        const int threads = 256;
        pad_scatter_generic<<<(total + threads - 1) / threads, threads>>>(
            (const float4*)d_in[0], (float4*)d_out, total, F4, max_sl);
    }
}

// round 3
// speedup vs baseline: 1.0338x; 1.0330x over previous
#include <cuda_runtime.h>
#include <cstdint>

// ---------------------------------------------------------------------------
// BatchedSequences: scatter concatenated rows S[T,F] into padded out[B,MAX,F],
// zero-filling padding. HBM-roofline copy.
// R3: fully fused single kernel (B<=32 fast path). Each warp redundantly
//     lane-loads the 32 lengths (L2-hot), detects int32/int64 via sum==T,
//     and computes off[b] with a warp scan. No prologue kernel, no smem.
// ---------------------------------------------------------------------------

#define MAX_B 4096
__device__ int       g_len[MAX_B];
__device__ long long g_off[MAX_B];

// ---- generic fallback path (any B / shapes) --------------------------------
__global__ void build_offsets_kernel(const void* __restrict__ lens_raw,
                                     int B, long long T) {
    __shared__ long long s32sum_sh;
    if (threadIdx.x == 0) {
        const int* v32 = (const int*)lens_raw;
        long long s = 0;
        #pragma unroll 4
        for (int i = 0; i < B; ++i) s += (long long)v32[i];
        s32sum_sh = s;
    }
    __syncthreads();
    const bool is32 = (s32sum_sh == T);
    if (threadIdx.x == 0) {
        const int* v32 = (const int*)lens_raw;
        const long long* v64 = (const long long*)lens_raw;
        long long off = 0;
        for (int i = 0; i < B; ++i) {
            long long L = is32 ? (long long)v32[i] : v64[i];
            g_len[i] = (int)L;
            g_off[i] = off;
            off += L;
        }
    }
}

__global__ void __launch_bounds__(256)
pad_scatter_generic(const float4* __restrict__ in4,
                    float4* __restrict__ out4,
                    int total, int F4, int max_sl) {
    int idx = blockIdx.x * blockDim.x + threadIdx.x;
    if (idx >= total) return;
    int c   = idx % F4;
    int row = idx / F4;
    int b   = row / max_sl;
    int p   = row - b * max_sl;
    float4 v = make_float4(0.f, 0.f, 0.f, 0.f);
    if (p < g_len[b])
        v = __ldcs(&in4[(g_off[b] + (long long)p) * F4 + c]);
    __stcs(&out4[idx], v);
}

// ---- fused fast path (B <= 32, F4/MAX powers of two) ------------------------
// 256 threads x 4 float4 = 1024 contiguous float4 per block; 1024 divides
// MAX*F4 so the batch index b is block-uniform. Each warp computes len[b] /
// off[b] itself: lane-parallel length load + warp scan (no barrier, no smem).
template <int F4_LOG2, int MAX_LOG2>
__global__ void __launch_bounds__(256)
fused_pad_scatter(const float4* __restrict__ in4,
                  float4* __restrict__ out4,
                  const void* __restrict__ lens_raw,
                  int B, long long T) {
    constexpr int F4 = 1 << F4_LOG2;
    constexpr unsigned FULL = 0xFFFFFFFFu;

    const int tid  = threadIdx.x;
    const int lane = tid & 31;
    const int base = (int)blockIdx.x * 1024;
    const int b    = base >> (F4_LOG2 + MAX_LOG2);

    // lengths: int32 interpretation is always in-bounds (B*4 bytes); its sum
    // equals T iff the buffer really is int32. Otherwise reload as int64.
    const int* v32 = (const int*)lens_raw;
    int x32 = (lane < B) ? __ldg(&v32[lane]) : 0;
    long long s = (long long)x32;
    #pragma unroll
    for (int d = 16; d; d >>= 1)
        s += __shfl_xor_sync(FULL, s, d);
    int val = x32;
    if (s != T) {                           // warp-uniform branch: int64 layout
        const long long* v64 = (const long long*)lens_raw;
        val = (lane < B) ? (int)__ldg(&v64[lane]) : 0;
    }
    int incl = val;                          // inclusive warp scan
    #pragma unroll
    for (int d = 1; d < 32; d <<= 1) {
        int y = __shfl_up_sync(FULL, incl, d);
        if (lane >= d) incl += y;
    }
    const int len = __shfl_sync(FULL, val, b);
    const int off = __shfl_sync(FULL, incl - val, b);

    // main copy: 4 independent float4 per thread (MLP=4), streaming hints.
    int   idx[4], p[4];
    float4 v[4];
    #pragma unroll
    for (int k = 0; k < 4; ++k) {
        idx[k] = base + tid + k * 256;
        p[k]   = (idx[k] >> F4_LOG2) & ((1 << MAX_LOG2) - 1);
        v[k]   = make_float4(0.f, 0.f, 0.f, 0.f);
    }
    #pragma unroll
    for (int k = 0; k < 4; ++k) {
        if (p[k] < len) {
            int c = idx[k] & (F4 - 1);
            v[k] = __ldcs(&in4[(off + p[k]) * F4 + c]);
        }
    }
    #pragma unroll
    for (int k = 0; k < 4; ++k)
        __stcs(&out4[idx[k]], v[k]);
}

extern "C" void kernel_launch(void* const* d_in, const int* in_sizes, int n_in,
                              void* d_out, int out_size) {
    const int F  = 512;
    const int F4 = F / 4;                                    // 128
    const int B  = in_sizes[1];
    const long long T = (long long)in_sizes[0] / F;
    const int max_sl = (int)((long long)out_size / ((long long)B * F));
    const int total  = out_size / 4;                         // float4 count

    if (F4 == 128 && max_sl == 4096 && B <= 32 && (total % 1024) == 0) {
        fused_pad_scatter<7, 12><<<total / 1024, 256>>>(
            (const float4*)d_in[0], (float4*)d_out, d_in[1], B, T);
    } else {
        build_offsets_kernel<<<1, 256>>>(d_in[1], B, T);
        pad_scatter_generic<<<(total + 255) / 256, 256>>>(
            (const float4*)d_in[0], (float4*)d_out, total, F4, max_sl);
    }
}